// round 2
// baseline (speedup 1.0000x reference)
#include <cuda_runtime.h>
#include <math.h>

#define NN 30000
#define EE 480000
#define CC 32
#define LL 2
#define PP 7
#define HH 4
#define DHH 8
#define NTT 15
#define EPSF 1e-8f
#define FULLMASK 0xffffffffu

// ---------------- scratch (device globals; no allocation allowed) ----------------
__device__ float g_r[EE];
__device__ float g_Y1[EE * 3];
__device__ float g_Y2[EE * 5];
__device__ float g_hidden[EE * CC];
__device__ float g_m0[EE * CC];
__device__ float g_logits[EE * HH];
__device__ float g_qn[NN * CC];
__device__ float g_mx[NN * HH];
__device__ float g_den[NN * HH];
__device__ float g_f0[2][NN * CC];
__device__ float g_f1[2][NN * 3 * CC];
__device__ float g_f2[2][NN * 5 * CC];
__device__ float g_agg0[NN * CC];
__device__ float g_agg1[NN * 3 * CC];
__device__ float g_agg2[NN * 5 * CC];

__device__ __forceinline__ void atomicMaxF(float* addr, float v) {
    if (v >= 0.0f) atomicMax((int*)addr, __float_as_int(v));
    else           atomicMin((unsigned int*)addr, __float_as_uint(v));
}

// ---------------- init: f0 = node_l0, f1 = f2 = 0 ----------------
__global__ void k_init(const float* __restrict__ node_l0) {
    int i = blockIdx.x * blockDim.x + threadIdx.x;
    if (i < NN * CC)     g_f0[0][i] = node_l0[i];
    if (i < NN * 3 * CC) g_f1[0][i] = 0.0f;
    if (i < NN * 5 * CC) g_f2[0][i] = 0.0f;
}

// ---------------- per-edge geometry: r, Y1, Y2 ----------------
__global__ void k_geo(const float* __restrict__ pos,
                      const int* __restrict__ src, const int* __restrict__ dst) {
    int e = blockIdx.x * blockDim.x + threadIdx.x;
    if (e >= EE) return;
    int s = src[e], d = dst[e];
    float rx = pos[d * 3 + 0] - pos[s * 3 + 0];
    float ry = pos[d * 3 + 1] - pos[s * 3 + 1];
    float rz = pos[d * 3 + 2] - pos[s * 3 + 2];
    float r = sqrtf(rx * rx + ry * ry + rz * rz + EPSF);
    float x = rx / r, y = ry / r, z = rz / r;
    g_r[e] = r;
    g_Y1[e * 3 + 0] = x;
    g_Y1[e * 3 + 1] = y;
    g_Y1[e * 3 + 2] = z;
    g_Y2[e * 5 + 0] = x * y;
    g_Y2[e * 5 + 1] = y * z;
    g_Y2[e * 5 + 2] = 3.0f * z * z - 1.0f;
    g_Y2[e * 5 + 3] = x * z;
    g_Y2[e * 5 + 4] = x * x - y * y;
}

// ---------------- per-layer prep: qn = f0 @ Wq, reset accumulators ----------------
__global__ __launch_bounds__(256) void k_prep(const float* __restrict__ Wq, int l, int cur) {
    int n = (blockIdx.x * blockDim.x + threadIdx.x) >> 5;
    int lane = threadIdx.x & 31;
    if (n >= NN) return;
    const float* W = Wq + l * CC * CC;
    float f0v = g_f0[cur][n * CC + lane];
    float q = 0.0f;
#pragma unroll
    for (int c = 0; c < CC; c++)
        q = fmaf(__shfl_sync(FULLMASK, f0v, c), W[c * CC + lane], q);
    g_qn[n * CC + lane] = q;
    if (lane < HH) {
        g_mx[n * HH + lane] = __int_as_float(0xff800000);  // -inf
        g_den[n * HH + lane] = 0.0f;
    }
    g_agg0[n * CC + lane] = 0.0f;
#pragma unroll
    for (int m = 0; m < 3; m++) g_agg1[n * 3 * CC + m * CC + lane] = 0.0f;
#pragma unroll
    for (int m = 0; m < 5; m++) g_agg2[n * 5 * CC + m * CC + lane] = 0.0f;
}

// ---------------- edge pass 1: radial MLP (w0..w2), m0, k, logits, segment max ----------------
__global__ __launch_bounds__(256) void k_edge1(
    const float* __restrict__ edge_feat,
    const int* __restrict__ src, const int* __restrict__ dst,
    const float* __restrict__ Wr1, const float* __restrict__ br1,
    const float* __restrict__ Wr2, const float* __restrict__ Wk,
    int l, int cur)
{
    int e = (blockIdx.x * blockDim.x + threadIdx.x) >> 5;
    int lane = threadIdx.x & 31;
    if (e >= EE) return;
    int s = src[e], d = dst[e];

    float ef = edge_feat[e * CC + lane];
    float r = g_r[e];

    // hidden = relu([r; edge_feat] @ Wr1[l] + br1[l])
    const float* W1 = Wr1 + l * 33 * CC;
    float h = fmaf(r, W1[lane], br1[l * CC + lane]);
#pragma unroll
    for (int i = 0; i < CC; i++)
        h = fmaf(__shfl_sync(FULLMASK, ef, i), W1[(i + 1) * CC + lane], h);
    h = fmaxf(h, 0.0f);
    g_hidden[e * CC + lane] = h;

    // w0..w2 = hidden @ Wr2[l][:, 0:96]
    float w0 = 0.0f, w1 = 0.0f, w2 = 0.0f;
    const float* W2 = Wr2 + l * CC * PP * CC;
#pragma unroll
    for (int j = 0; j < CC; j++) {
        float hj = __shfl_sync(FULLMASK, h, j);
        const float* Wj = W2 + j * PP * CC;
        w0 = fmaf(hj, Wj[lane], w0);
        w1 = fmaf(hj, Wj[CC + lane], w1);
        w2 = fmaf(hj, Wj[2 * CC + lane], w2);
    }

    // gather src features (SoA layouts: f1 (N,3,C), f2 (N,5,C))
    float f0s = g_f0[cur][s * CC + lane];
    float d1 = 0.0f;
#pragma unroll
    for (int m = 0; m < 3; m++)
        d1 = fmaf(g_f1[cur][s * 3 * CC + m * CC + lane], g_Y1[e * 3 + m], d1);
    float d2 = 0.0f;
#pragma unroll
    for (int m = 0; m < 5; m++)
        d2 = fmaf(g_f2[cur][s * 5 * CC + m * CC + lane], g_Y2[e * 5 + m], d2);

    float m0 = w0 * f0s + w1 * d1 + w2 * d2;
    g_m0[e * CC + lane] = m0;

    // k = m0 @ Wk[l]
    const float* WK = Wk + l * CC * CC;
    float k = 0.0f;
#pragma unroll
    for (int c = 0; c < CC; c++)
        k = fmaf(__shfl_sync(FULLMASK, m0, c), WK[c * CC + lane], k);

    float prod = g_qn[d * CC + lane] * k;
    // reduce within 8-lane head groups
    prod += __shfl_xor_sync(FULLMASK, prod, 4);
    prod += __shfl_xor_sync(FULLMASK, prod, 2);
    prod += __shfl_xor_sync(FULLMASK, prod, 1);

    if ((lane & 7) == 0) {
        int hh = lane >> 3;
        float logit = prod * 0.35355339059327373f;  // 1/sqrt(8)
        g_logits[e * HH + hh] = logit;
        atomicMaxF(&g_mx[d * HH + hh], logit);
    }
}

// ---------------- edge pass 2: softmax denominator ----------------
__global__ void k_den(const int* __restrict__ dst) {
    int e = blockIdx.x * blockDim.x + threadIdx.x;
    if (e >= EE) return;
    int d = dst[e];
#pragma unroll
    for (int h = 0; h < HH; h++) {
        float v = expf(g_logits[e * HH + h] - g_mx[d * HH + h]);
        atomicAdd(&g_den[d * HH + h], v);
    }
}

// ---------------- edge pass 3: alpha, w3..w6, m1/m2, aggregation ----------------
__global__ __launch_bounds__(256) void k_edge2(
    const int* __restrict__ src, const int* __restrict__ dst,
    const float* __restrict__ Wr2, int l, int cur)
{
    int e = (blockIdx.x * blockDim.x + threadIdx.x) >> 5;
    int lane = threadIdx.x & 31;
    if (e >= EE) return;
    int s = src[e], d = dst[e];

    int hh = lane >> 3;
    float alpha = expf(g_logits[e * HH + hh] - g_mx[d * HH + hh]) /
                  (g_den[d * HH + hh] + EPSF);

    float hid = g_hidden[e * CC + lane];
    float w3 = 0.0f, w4 = 0.0f, w5 = 0.0f, w6 = 0.0f;
    const float* W2 = Wr2 + l * CC * PP * CC + 3 * CC;
#pragma unroll
    for (int j = 0; j < CC; j++) {
        float hj = __shfl_sync(FULLMASK, hid, j);
        const float* Wj = W2 + j * PP * CC;
        w3 = fmaf(hj, Wj[lane], w3);
        w4 = fmaf(hj, Wj[CC + lane], w4);
        w5 = fmaf(hj, Wj[2 * CC + lane], w5);
        w6 = fmaf(hj, Wj[3 * CC + lane], w6);
    }

    float f0s = g_f0[cur][s * CC + lane];
    float m0v = g_m0[e * CC + lane];
    atomicAdd(&g_agg0[d * CC + lane], alpha * m0v);

#pragma unroll
    for (int m = 0; m < 3; m++) {
        float f1s = g_f1[cur][s * 3 * CC + m * CC + lane];
        float m1 = w3 * f0s * g_Y1[e * 3 + m] + w4 * f1s;
        atomicAdd(&g_agg1[d * 3 * CC + m * CC + lane], alpha * m1);
    }
#pragma unroll
    for (int m = 0; m < 5; m++) {
        float f2s = g_f2[cur][s * 5 * CC + m * CC + lane];
        float m2 = w5 * f0s * g_Y2[e * 5 + m] + w6 * f2s;
        atomicAdd(&g_agg2[d * 5 * CC + m * CC + lane], alpha * m2);
    }
}

// ---------------- per-node update ----------------
__global__ __launch_bounds__(256) void k_node(
    const float* __restrict__ Ws0, const float* __restrict__ Ws1,
    const float* __restrict__ Ws2, const float* __restrict__ Wsk,
    int l, int cur)
{
    int n = (blockIdx.x * blockDim.x + threadIdx.x) >> 5;
    int lane = threadIdx.x & 31;
    if (n >= NN) return;
    int nxt = cur ^ 1;
    const float* W0 = Ws0 + l * CC * CC;
    const float* W1 = Ws1 + l * CC * CC;
    const float* W2 = Ws2 + l * CC * CC;
    const float* WS = Wsk + l * CC * CC;

    float a0 = g_agg0[n * CC + lane];
    float f0o = g_f0[cur][n * CC + lane];
    float o0 = 0.0f;
#pragma unroll
    for (int c = 0; c < CC; c++) {
        float ac = __shfl_sync(FULLMASK, a0, c);
        float fc = __shfl_sync(FULLMASK, f0o, c);
        o0 = fmaf(ac, W0[c * CC + lane], o0);
        o0 = fmaf(fc, WS[c * CC + lane], o0);
    }
    g_f0[nxt][n * CC + lane] = o0;

#pragma unroll
    for (int m = 0; m < 3; m++) {
        float a1 = g_agg1[n * 3 * CC + m * CC + lane];
        float o = 0.0f;
#pragma unroll
        for (int c = 0; c < CC; c++)
            o = fmaf(__shfl_sync(FULLMASK, a1, c), W1[c * CC + lane], o);
        g_f1[nxt][n * 3 * CC + m * CC + lane] = o;
    }
#pragma unroll
    for (int m = 0; m < 5; m++) {
        float a2 = g_agg2[n * 5 * CC + m * CC + lane];
        float o = 0.0f;
#pragma unroll
        for (int c = 0; c < CC; c++)
            o = fmaf(__shfl_sync(FULLMASK, a2, c), W2[c * CC + lane], o);
        g_f2[nxt][n * 5 * CC + m * CC + lane] = o;
    }
}

// ---------------- output: hs0 = f0 @ Wout ; cs = hs0 @ Wc ----------------
__global__ __launch_bounds__(256) void k_out(
    const float* __restrict__ Wout, const float* __restrict__ Wc,
    float* __restrict__ out, int fin)
{
    int n = (blockIdx.x * blockDim.x + threadIdx.x) >> 5;
    int lane = threadIdx.x & 31;
    if (n >= NN) return;
    float f0v = g_f0[fin][n * CC + lane];
    float hs = 0.0f;
#pragma unroll
    for (int c = 0; c < CC; c++)
        hs = fmaf(__shfl_sync(FULLMASK, f0v, c), Wout[c * CC + lane], hs);
    out[n * CC + lane] = hs;

    int t = (lane < NTT) ? lane : 0;
    float cs = 0.0f;
#pragma unroll
    for (int c = 0; c < CC; c++)
        cs = fmaf(__shfl_sync(FULLMASK, hs, c), Wc[c * NTT + t], cs);
    if (lane < NTT) out[NN * CC + n * NTT + lane] = cs;
}

// ---------------- launch ----------------
extern "C" void kernel_launch(void* const* d_in, const int* in_sizes, int n_in,
                              void* d_out, int out_size) {
    (void)in_sizes; (void)n_in; (void)out_size;
    const float* pos       = (const float*)d_in[0];
    const float* node_l0   = (const float*)d_in[1];
    const float* edge_feat = (const float*)d_in[2];
    const int*   esrc      = (const int*)d_in[3];
    const int*   edst      = (const int*)d_in[4];
    const float* Wr1       = (const float*)d_in[5];
    const float* br1       = (const float*)d_in[6];
    const float* Wr2       = (const float*)d_in[7];
    const float* Wq        = (const float*)d_in[8];
    const float* Wk        = (const float*)d_in[9];
    const float* Ws0       = (const float*)d_in[10];
    const float* Ws1       = (const float*)d_in[11];
    const float* Ws2       = (const float*)d_in[12];
    const float* Wsk       = (const float*)d_in[13];
    const float* Wout      = (const float*)d_in[14];
    const float* Wc        = (const float*)d_in[15];
    float* out = (float*)d_out;

    k_init<<<(NN * 5 * CC + 255) / 256, 256>>>(node_l0);
    k_geo<<<(EE + 255) / 256, 256>>>(pos, esrc, edst);
    for (int l = 0; l < LL; l++) {
        int cur = l & 1;
        k_prep<<<(NN * 32) / 256, 256>>>(Wq, l, cur);
        k_edge1<<<(EE * 32) / 256, 256>>>(edge_feat, esrc, edst, Wr1, br1, Wr2, Wk, l, cur);
        k_den<<<(EE + 255) / 256, 256>>>(edst);
        k_edge2<<<(EE * 32) / 256, 256>>>(esrc, edst, Wr2, l, cur);
        k_node<<<(NN * 32) / 256, 256>>>(Ws0, Ws1, Ws2, Wsk, l, cur);
    }
    k_out<<<(NN * 32) / 256, 256>>>(Wout, Wc, out, 0);
}

// round 3
// speedup vs baseline: 1.4257x; 1.4257x over previous
#include <cuda_runtime.h>
#include <math.h>

#define NN 30000
#define EE 480000
#define CC 32
#define LL 2
#define PP 7
#define HH 4
#define NTT 15
#define EPSF 1e-8f
#define FULLMASK 0xffffffffu
#define EPW 4   // edges per warp

// ---------------- scratch (device globals; no allocation allowed) ----------------
__device__ float g_r[EE];
__device__ float g_Y1[EE * 3];
__device__ float g_Y2[EE * 5];
__device__ float g_hidden[EE * CC];
__device__ float g_m0[EE * CC];
__device__ float g_logits[EE * HH];
__device__ float g_B[NN * HH * CC];        // B[n][h][c]
__device__ float g_mx[NN * HH];
__device__ float g_den[NN * HH];
__device__ float g_f0[2][NN * CC];
__device__ float g_f1[2][NN * 3 * CC];
__device__ float g_f2[2][NN * 5 * CC];
__device__ float g_aggP[NN * CC * 12];     // packed: [n][c][12] = {agg0, m1x3, m2x5, pad3}

__device__ __forceinline__ void atomicMaxF(float* addr, float v) {
    if (v >= 0.0f) atomicMax((int*)addr, __float_as_int(v));
    else           atomicMin((unsigned int*)addr, __float_as_uint(v));
}

__device__ __forceinline__ void redAdd4(float* a, float4 v) {
    asm volatile("red.global.add.v4.f32 [%0], {%1,%2,%3,%4};"
                 :: "l"(a), "f"(v.x), "f"(v.y), "f"(v.z), "f"(v.w) : "memory");
}
__device__ __forceinline__ void redAdd1(float* a, float v) {
    asm volatile("red.global.add.f32 [%0], %1;" :: "l"(a), "f"(v) : "memory");
}

// ---------------- init ----------------
__global__ void k_init(const float* __restrict__ node_l0) {
    int i = blockIdx.x * blockDim.x + threadIdx.x;
    if (i < NN * CC)     g_f0[0][i] = node_l0[i];
    if (i < NN * 3 * CC) g_f1[0][i] = 0.0f;
    if (i < NN * 5 * CC) g_f2[0][i] = 0.0f;
}

// ---------------- per-edge geometry ----------------
__global__ void k_geo(const float* __restrict__ pos,
                      const int* __restrict__ src, const int* __restrict__ dst) {
    int e = blockIdx.x * blockDim.x + threadIdx.x;
    if (e >= EE) return;
    int s = src[e], d = dst[e];
    float rx = pos[d * 3 + 0] - pos[s * 3 + 0];
    float ry = pos[d * 3 + 1] - pos[s * 3 + 1];
    float rz = pos[d * 3 + 2] - pos[s * 3 + 2];
    float r = sqrtf(rx * rx + ry * ry + rz * rz + EPSF);
    float x = rx / r, y = ry / r, z = rz / r;
    g_r[e] = r;
    g_Y1[e * 3 + 0] = x;
    g_Y1[e * 3 + 1] = y;
    g_Y1[e * 3 + 2] = z;
    g_Y2[e * 5 + 0] = x * y;
    g_Y2[e * 5 + 1] = y * z;
    g_Y2[e * 5 + 2] = 3.0f * z * z - 1.0f;
    g_Y2[e * 5 + 3] = x * z;
    g_Y2[e * 5 + 4] = x * x - y * y;
}

// ---------------- per-layer prep: q = f0@Wq, B[n,h,c] = sum_{c' in h} Wk[c,c'] q[c'] ----------------
__global__ __launch_bounds__(256) void k_prep(const float* __restrict__ Wq,
                                              const float* __restrict__ Wk,
                                              int l, int cur) {
    __shared__ float sWk[CC * 33];   // padded transposed access
    const float* WK = Wk + l * CC * CC;
    for (int idx = threadIdx.x; idx < CC * CC; idx += 256) {
        int r = idx >> 5, c = idx & 31;
        sWk[r * 33 + c] = WK[idx];
    }
    __syncthreads();

    int n = (blockIdx.x * blockDim.x + threadIdx.x) >> 5;
    int lane = threadIdx.x & 31;
    if (n >= NN) return;

    const float* W = Wq + l * CC * CC;
    float f0v = g_f0[cur][n * CC + lane];
    float q = 0.0f;
#pragma unroll
    for (int c = 0; c < CC; c++)
        q = fmaf(__shfl_sync(FULLMASK, f0v, c), W[c * CC + lane], q);

#pragma unroll
    for (int hh = 0; hh < HH; hh++) {
        float acc = 0.0f;
#pragma unroll
        for (int i = 0; i < 8; i++) {
            int cp = hh * 8 + i;
            acc = fmaf(sWk[lane * 33 + cp], __shfl_sync(FULLMASK, q, cp), acc);
        }
        g_B[n * (HH * CC) + hh * CC + lane] = acc;
    }

    if (lane < HH) {
        g_mx[n * HH + lane] = __int_as_float(0xff800000);
        g_den[n * HH + lane] = 0.0f;
    }
    // zero packed aggregation slot (12 floats per lane)
    float4 z = make_float4(0.f, 0.f, 0.f, 0.f);
    float4* pb = (float4*)(g_aggP + (size_t)(n * CC + lane) * 12);
    pb[0] = z; pb[1] = z; pb[2] = z;
}

// ---------------- edge pass 1: radial MLP (w0..w2), m0, logits, segment max ----------------
__global__ __launch_bounds__(256) void k_edge1(
    const float* __restrict__ edge_feat,
    const int* __restrict__ src, const int* __restrict__ dst,
    const float* __restrict__ Wr1, const float* __restrict__ br1,
    const float* __restrict__ Wr2,
    int l, int cur)
{
    int warp = (blockIdx.x * blockDim.x + threadIdx.x) >> 5;
    int lane = threadIdx.x & 31;
    int e0 = warp * EPW;
    if (e0 >= EE) return;

    int s[EPW], d[EPW];
    float ef[EPW], h[EPW];
#pragma unroll
    for (int ee = 0; ee < EPW; ee++) {
        s[ee] = src[e0 + ee];
        d[ee] = dst[e0 + ee];
        ef[ee] = edge_feat[(e0 + ee) * CC + lane];
    }

    // hidden = relu([r; ef] @ Wr1 + br1)
    const float* W1 = Wr1 + l * 33 * CC;
    float b = br1[l * CC + lane];
    float w1l = W1[lane];
#pragma unroll
    for (int ee = 0; ee < EPW; ee++)
        h[ee] = fmaf(g_r[e0 + ee], w1l, b);
#pragma unroll
    for (int i = 0; i < CC; i++) {
        float w = W1[(i + 1) * CC + lane];
#pragma unroll
        for (int ee = 0; ee < EPW; ee++)
            h[ee] = fmaf(__shfl_sync(FULLMASK, ef[ee], i), w, h[ee]);
    }
#pragma unroll
    for (int ee = 0; ee < EPW; ee++) {
        h[ee] = fmaxf(h[ee], 0.0f);
        g_hidden[(e0 + ee) * CC + lane] = h[ee];
    }

    // w0..w2 = hidden @ Wr2[:, 0:96]
    float w0[EPW], w1_[EPW], w2_[EPW];
#pragma unroll
    for (int ee = 0; ee < EPW; ee++) { w0[ee] = 0.f; w1_[ee] = 0.f; w2_[ee] = 0.f; }
    const float* W2 = Wr2 + l * CC * PP * CC;
#pragma unroll
    for (int j = 0; j < CC; j++) {
        const float* Wj = W2 + j * PP * CC;
        float a = Wj[lane], bb = Wj[CC + lane], cc = Wj[2 * CC + lane];
#pragma unroll
        for (int ee = 0; ee < EPW; ee++) {
            float hj = __shfl_sync(FULLMASK, h[ee], j);
            w0[ee] = fmaf(hj, a, w0[ee]);
            w1_[ee] = fmaf(hj, bb, w1_[ee]);
            w2_[ee] = fmaf(hj, cc, w2_[ee]);
        }
    }

#pragma unroll
    for (int ee = 0; ee < EPW; ee++) {
        int e = e0 + ee, ss = s[ee], dd = d[ee];
        float f0s = g_f0[cur][ss * CC + lane];
        float d1 = 0.0f;
#pragma unroll
        for (int m = 0; m < 3; m++)
            d1 = fmaf(g_f1[cur][ss * 3 * CC + m * CC + lane], g_Y1[e * 3 + m], d1);
        float d2 = 0.0f;
#pragma unroll
        for (int m = 0; m < 5; m++)
            d2 = fmaf(g_f2[cur][ss * 5 * CC + m * CC + lane], g_Y2[e * 5 + m], d2);

        float m0 = w0[ee] * f0s + w1_[ee] * d1 + w2_[ee] * d2;
        g_m0[e * CC + lane] = m0;

        // logits_h = sum_c m0[c] * B[dd,h,c]
#pragma unroll
        for (int hh = 0; hh < HH; hh++) {
            float p = m0 * g_B[dd * (HH * CC) + hh * CC + lane];
            p += __shfl_xor_sync(FULLMASK, p, 16);
            p += __shfl_xor_sync(FULLMASK, p, 8);
            p += __shfl_xor_sync(FULLMASK, p, 4);
            p += __shfl_xor_sync(FULLMASK, p, 2);
            p += __shfl_xor_sync(FULLMASK, p, 1);
            if (lane == 0) {
                float logit = p * 0.35355339059327373f;  // 1/sqrt(8)
                g_logits[e * HH + hh] = logit;
                atomicMaxF(&g_mx[dd * HH + hh], logit);
            }
        }
    }
}

// ---------------- edge pass 2: softmax denominator ----------------
__global__ void k_den(const int* __restrict__ dst) {
    int e = blockIdx.x * blockDim.x + threadIdx.x;
    if (e >= EE) return;
    int d = dst[e];
#pragma unroll
    for (int h = 0; h < HH; h++) {
        float v = expf(g_logits[e * HH + h] - g_mx[d * HH + h]);
        atomicAdd(&g_den[d * HH + h], v);
    }
}

// ---------------- edge pass 3: alpha, w3..w6, m1/m2, aggregation ----------------
__global__ __launch_bounds__(256) void k_edge2(
    const int* __restrict__ src, const int* __restrict__ dst,
    const float* __restrict__ Wr2, int l, int cur)
{
    int warp = (blockIdx.x * blockDim.x + threadIdx.x) >> 5;
    int lane = threadIdx.x & 31;
    int e0 = warp * EPW;
    if (e0 >= EE) return;

    float h[EPW];
#pragma unroll
    for (int ee = 0; ee < EPW; ee++)
        h[ee] = g_hidden[(e0 + ee) * CC + lane];

    float w3[EPW], w4[EPW], w5[EPW], w6[EPW];
#pragma unroll
    for (int ee = 0; ee < EPW; ee++) { w3[ee] = 0.f; w4[ee] = 0.f; w5[ee] = 0.f; w6[ee] = 0.f; }
    const float* W2 = Wr2 + l * CC * PP * CC + 3 * CC;
#pragma unroll
    for (int j = 0; j < CC; j++) {
        const float* Wj = W2 + j * PP * CC;
        float a = Wj[lane], bb = Wj[CC + lane], cc = Wj[2 * CC + lane], dd2 = Wj[3 * CC + lane];
#pragma unroll
        for (int ee = 0; ee < EPW; ee++) {
            float hj = __shfl_sync(FULLMASK, h[ee], j);
            w3[ee] = fmaf(hj, a, w3[ee]);
            w4[ee] = fmaf(hj, bb, w4[ee]);
            w5[ee] = fmaf(hj, cc, w5[ee]);
            w6[ee] = fmaf(hj, dd2, w6[ee]);
        }
    }

    int hsel = lane >> 3;
#pragma unroll
    for (int ee = 0; ee < EPW; ee++) {
        int e = e0 + ee;
        int ss = src[e], dd = dst[e];
        float alpha = expf(g_logits[e * HH + hsel] - g_mx[dd * HH + hsel]) /
                      (g_den[dd * HH + hsel] + EPSF);

        float f0s = g_f0[cur][ss * CC + lane];
        float m0v = g_m0[e * CC + lane];
        float a0 = alpha * m0v;

        float a1m[3];
#pragma unroll
        for (int m = 0; m < 3; m++) {
            float f1s = g_f1[cur][ss * 3 * CC + m * CC + lane];
            a1m[m] = alpha * (w3[ee] * f0s * g_Y1[e * 3 + m] + w4[ee] * f1s);
        }
        float a2m[5];
#pragma unroll
        for (int m = 0; m < 5; m++) {
            float f2s = g_f2[cur][ss * 5 * CC + m * CC + lane];
            a2m[m] = alpha * (w5[ee] * f0s * g_Y2[e * 5 + m] + w6[ee] * f2s);
        }

        float* base = g_aggP + (size_t)(dd * CC + lane) * 12;
        redAdd4(base,     make_float4(a0,     a1m[0], a1m[1], a1m[2]));
        redAdd4(base + 4, make_float4(a2m[0], a2m[1], a2m[2], a2m[3]));
        redAdd1(base + 8, a2m[4]);
    }
}

// ---------------- per-node update ----------------
__global__ __launch_bounds__(256) void k_node(
    const float* __restrict__ Ws0, const float* __restrict__ Ws1,
    const float* __restrict__ Ws2, const float* __restrict__ Wsk,
    int l, int cur)
{
    int n = (blockIdx.x * blockDim.x + threadIdx.x) >> 5;
    int lane = threadIdx.x & 31;
    if (n >= NN) return;
    int nxt = cur ^ 1;
    const float* W0 = Ws0 + l * CC * CC;
    const float* W1 = Ws1 + l * CC * CC;
    const float* W2 = Ws2 + l * CC * CC;
    const float* WS = Wsk + l * CC * CC;

    const float* base = g_aggP + (size_t)(n * CC + lane) * 12;
    float4 pa = *(const float4*)(base);
    float4 pb = *(const float4*)(base + 4);
    float a24 = base[8];
    float a0 = pa.x;
    float a1m[3] = {pa.y, pa.z, pa.w};
    float a2m[5] = {pb.x, pb.y, pb.z, pb.w, a24};

    float f0o = g_f0[cur][n * CC + lane];
    float o0 = 0.0f;
#pragma unroll
    for (int c = 0; c < CC; c++) {
        float ac = __shfl_sync(FULLMASK, a0, c);
        float fc = __shfl_sync(FULLMASK, f0o, c);
        o0 = fmaf(ac, W0[c * CC + lane], o0);
        o0 = fmaf(fc, WS[c * CC + lane], o0);
    }
    g_f0[nxt][n * CC + lane] = o0;

#pragma unroll
    for (int m = 0; m < 3; m++) {
        float o = 0.0f;
#pragma unroll
        for (int c = 0; c < CC; c++)
            o = fmaf(__shfl_sync(FULLMASK, a1m[m], c), W1[c * CC + lane], o);
        g_f1[nxt][n * 3 * CC + m * CC + lane] = o;
    }
#pragma unroll
    for (int m = 0; m < 5; m++) {
        float o = 0.0f;
#pragma unroll
        for (int c = 0; c < CC; c++)
            o = fmaf(__shfl_sync(FULLMASK, a2m[m], c), W2[c * CC + lane], o);
        g_f2[nxt][n * 5 * CC + m * CC + lane] = o;
    }
}

// ---------------- output ----------------
__global__ __launch_bounds__(256) void k_out(
    const float* __restrict__ Wout, const float* __restrict__ Wc,
    float* __restrict__ out, int fin)
{
    int n = (blockIdx.x * blockDim.x + threadIdx.x) >> 5;
    int lane = threadIdx.x & 31;
    if (n >= NN) return;
    float f0v = g_f0[fin][n * CC + lane];
    float hs = 0.0f;
#pragma unroll
    for (int c = 0; c < CC; c++)
        hs = fmaf(__shfl_sync(FULLMASK, f0v, c), Wout[c * CC + lane], hs);
    out[n * CC + lane] = hs;

    int t = (lane < NTT) ? lane : 0;
    float cs = 0.0f;
#pragma unroll
    for (int c = 0; c < CC; c++)
        cs = fmaf(__shfl_sync(FULLMASK, hs, c), Wc[c * NTT + t], cs);
    if (lane < NTT) out[NN * CC + n * NTT + lane] = cs;
}

// ---------------- launch ----------------
extern "C" void kernel_launch(void* const* d_in, const int* in_sizes, int n_in,
                              void* d_out, int out_size) {
    (void)in_sizes; (void)n_in; (void)out_size;
    const float* pos       = (const float*)d_in[0];
    const float* node_l0   = (const float*)d_in[1];
    const float* edge_feat = (const float*)d_in[2];
    const int*   esrc      = (const int*)d_in[3];
    const int*   edst      = (const int*)d_in[4];
    const float* Wr1       = (const float*)d_in[5];
    const float* br1       = (const float*)d_in[6];
    const float* Wr2       = (const float*)d_in[7];
    const float* Wq        = (const float*)d_in[8];
    const float* Wk        = (const float*)d_in[9];
    const float* Ws0       = (const float*)d_in[10];
    const float* Ws1       = (const float*)d_in[11];
    const float* Ws2       = (const float*)d_in[12];
    const float* Wsk       = (const float*)d_in[13];
    const float* Wout      = (const float*)d_in[14];
    const float* Wc        = (const float*)d_in[15];
    float* out = (float*)d_out;

    const int edgeWarps = EE / EPW;              // 120000
    const int edgeBlocks = edgeWarps / 8;        // 15000 (256 thr = 8 warps)

    k_init<<<(NN * 5 * CC + 255) / 256, 256>>>(node_l0);
    k_geo<<<(EE + 255) / 256, 256>>>(pos, esrc, edst);
    for (int l = 0; l < LL; l++) {
        int cur = l & 1;
        k_prep<<<(NN * 32) / 256, 256>>>(Wq, Wk, l, cur);
        k_edge1<<<edgeBlocks, 256>>>(edge_feat, esrc, edst, Wr1, br1, Wr2, l, cur);
        k_den<<<(EE + 255) / 256, 256>>>(edst);
        k_edge2<<<edgeBlocks, 256>>>(esrc, edst, Wr2, l, cur);
        k_node<<<(NN * 32) / 256, 256>>>(Ws0, Ws1, Ws2, Wsk, l, cur);
    }
    k_out<<<(NN * 32) / 256, 256>>>(Wout, Wc, out, 0);
}